// round 1
// baseline (speedup 1.0000x reference)
#include <cuda_runtime.h>
#include <cuda_bf16.h>
#include <cstdint>

// Problem constants
#define BW_   1024
#define NTOK  64
#define DIM_  512
#define NH_   16
#define HD_   32
#define NW_   64
#define TRIPLE 1536
#define SCALE_ 0.17677669529663687f

// Scratch (allocation-free rule: __device__ globals)
__device__ float g_qkv[(size_t)BW_ * NTOK * TRIPLE];   // (BW, N, 3*DIM)  ~402MB
__device__ float g_att[(size_t)BW_ * NTOK * DIM_];     // (BW, N, DIM)    ~134MB

// ---------------------------------------------------------------------------
// SGEMM (NT): C[m][n] = sum_k A[m][k] * B[n][k] + bias[n]
// A: MxK row-major, B: NnxK row-major, C: MxNn row-major.
// 128x128 tile, BK=16, 256 threads, 8x8 per-thread register tile.
// ---------------------------------------------------------------------------
__global__ __launch_bounds__(256) void sgemm_nt_bias(
    const float* __restrict__ A, const float* __restrict__ B,
    const float* __restrict__ bias, float* __restrict__ C,
    int M, int Nn, int K)
{
    constexpr int BM = 128, BN = 128, BK = 16;
    __shared__ float As[BK][BM];
    __shared__ float Bs[BK][BN];

    const int tid = threadIdx.x;
    const int m0 = blockIdx.y * BM;
    const int n0 = blockIdx.x * BN;
    const int tx = tid & 15;        // 0..15  (column group)
    const int ty = tid >> 4;        // 0..15  (row group)

    float acc[8][8];
    #pragma unroll
    for (int i = 0; i < 8; ++i)
        #pragma unroll
        for (int j = 0; j < 8; ++j) acc[i][j] = 0.f;

    for (int k0 = 0; k0 < K; k0 += BK) {
        // Load tiles: 128 rows x 16 k = 512 float4 per matrix; 2 per thread.
        #pragma unroll
        for (int l = 0; l < 2; ++l) {
            int lin = tid + l * 256;          // 0..511
            int row = lin >> 2;               // 0..127
            int kq  = (lin & 3) << 2;         // 0,4,8,12
            float4 av = *(const float4*)(A + (size_t)(m0 + row) * K + k0 + kq);
            As[kq + 0][row] = av.x; As[kq + 1][row] = av.y;
            As[kq + 2][row] = av.z; As[kq + 3][row] = av.w;
            float4 bv = *(const float4*)(B + (size_t)(n0 + row) * K + k0 + kq);
            Bs[kq + 0][row] = bv.x; Bs[kq + 1][row] = bv.y;
            Bs[kq + 2][row] = bv.z; Bs[kq + 3][row] = bv.w;
        }
        __syncthreads();

        #pragma unroll
        for (int kk = 0; kk < BK; ++kk) {
            float a[8], b[8];
            #pragma unroll
            for (int i = 0; i < 8; ++i) a[i] = As[kk][ty * 8 + i];
            #pragma unroll
            for (int j = 0; j < 8; ++j) b[j] = Bs[kk][tx * 8 + j];
            #pragma unroll
            for (int i = 0; i < 8; ++i)
                #pragma unroll
                for (int j = 0; j < 8; ++j) acc[i][j] += a[i] * b[j];
        }
        __syncthreads();
    }

    // Epilogue with bias
    #pragma unroll
    for (int i = 0; i < 8; ++i) {
        int m = m0 + ty * 8 + i;
        #pragma unroll
        for (int j = 0; j < 8; j += 4) {
            int n = n0 + tx * 8 + j;
            float4 o;
            o.x = acc[i][j + 0] + bias[n + 0];
            o.y = acc[i][j + 1] + bias[n + 1];
            o.z = acc[i][j + 2] + bias[n + 2];
            o.w = acc[i][j + 3] + bias[n + 3];
            *(float4*)(C + (size_t)m * Nn + n) = o;
        }
    }
}

// ---------------------------------------------------------------------------
// Attention: one block per (head, window). 128 threads.
// q,k,v in smem (padded), scores + bias + mask, warp-per-row softmax, AV.
// ---------------------------------------------------------------------------
__global__ __launch_bounds__(128) void attn_kernel(
    const float* __restrict__ qkv,        // (BW, N, 1536)
    const float* __restrict__ mask,       // (NW, N, N)
    const float* __restrict__ table,      // (225, NH)
    const int*   __restrict__ rel_index,  // (N, N)
    float* __restrict__ out)              // (BW, N, DIM)
{
    const int h  = blockIdx.x;   // 0..15
    const int bw = blockIdx.y;   // 0..1023
    const int tid = threadIdx.x; // 0..127

    __shared__ float q[64][33];
    __shared__ float k[64][33];
    __shared__ float v[64][33];
    __shared__ float s[64][65];

    const float* base = qkv + (size_t)bw * NTOK * TRIPLE + h * HD_;
    #pragma unroll
    for (int r = 0; r < 16; ++r) {
        int lin = tid + r * 128;     // 0..2047
        int n = lin >> 5, d = lin & 31;
        q[n][d] = base[n * TRIPLE + d] * SCALE_;
        k[n][d] = base[n * TRIPLE + 512 + d];
        v[n][d] = base[n * TRIPLE + 1024 + d];
    }
    __syncthreads();

    // Scores: thread pair per row; each thread does 32 columns.
    const float* mrow = mask + (size_t)(bw & (NW_ - 1)) * (NTOK * NTOK);
    const int i = tid >> 1;
    const int jbase = (tid & 1) * 32;
    #pragma unroll 4
    for (int jj = 0; jj < 32; ++jj) {
        int j = jbase + jj;
        float a = 0.f;
        #pragma unroll
        for (int d = 0; d < 32; ++d) a += q[i][d] * k[j][d];
        a += table[rel_index[i * 64 + j] * NH_ + h] + mrow[i * 64 + j];
        s[i][j] = a;
    }
    __syncthreads();

    // Softmax: each warp handles 16 rows; full warp per row (2 elems/lane).
    const int warp = tid >> 5, lane = tid & 31;
    for (int rr = 0; rr < 16; ++rr) {
        int row = warp * 16 + rr;
        float a0 = s[row][lane], a1 = s[row][lane + 32];
        float m = fmaxf(a0, a1);
        #pragma unroll
        for (int o = 16; o > 0; o >>= 1) m = fmaxf(m, __shfl_xor_sync(0xffffffffu, m, o));
        float e0 = __expf(a0 - m), e1 = __expf(a1 - m);
        float sm = e0 + e1;
        #pragma unroll
        for (int o = 16; o > 0; o >>= 1) sm += __shfl_xor_sync(0xffffffffu, sm, o);
        float inv = 1.f / sm;
        s[row][lane] = e0 * inv;
        s[row][lane + 32] = e1 * inv;
    }
    __syncthreads();

    // AV: thread pair per row; each thread 16 of 32 head-dims.
    const int dbase = (tid & 1) * 16;
    float acc[16];
    #pragma unroll
    for (int t = 0; t < 16; ++t) acc[t] = 0.f;
    #pragma unroll 4
    for (int j = 0; j < 64; ++j) {
        float p = s[i][j];
        #pragma unroll
        for (int t = 0; t < 16; ++t) acc[t] += p * v[j][dbase + t];
    }
    float* orow = out + (size_t)bw * NTOK * DIM_ + i * DIM_ + h * HD_ + dbase;
    #pragma unroll
    for (int t = 0; t < 16; ++t) orow[t] = acc[t];
}

// ---------------------------------------------------------------------------
extern "C" void kernel_launch(void* const* d_in, const int* in_sizes, int n_in,
                              void* d_out, int out_size)
{
    const float* x        = (const float*)d_in[0];  // (BW, N, DIM)
    const float* mask     = (const float*)d_in[1];  // (NW, N, N)
    const float* qkv_w    = (const float*)d_in[2];  // (1536, 512)
    const float* qkv_b    = (const float*)d_in[3];  // (1536,)
    const float* table    = (const float*)d_in[4];  // (225, 16)
    const float* proj_w   = (const float*)d_in[5];  // (512, 512)
    const float* proj_b   = (const float*)d_in[6];  // (512,)
    const int*   rel_idx  = (const int*)d_in[7];    // (64, 64)
    float* out = (float*)d_out;

    float* qkv = nullptr;
    float* att = nullptr;
    cudaGetSymbolAddress((void**)&qkv, g_qkv);
    cudaGetSymbolAddress((void**)&att, g_att);

    const int M = BW_ * NTOK;   // 65536

    // 1) QKV projection: (65536x512) @ (1536x512)^T + b -> (65536x1536)
    {
        dim3 grid(TRIPLE / 128, M / 128);
        sgemm_nt_bias<<<grid, 256>>>(x, qkv_w, qkv_b, qkv, M, TRIPLE, DIM_);
    }
    // 2) Window attention per (head, window)
    {
        dim3 grid(NH_, BW_);
        attn_kernel<<<grid, 128>>>(qkv, mask, table, rel_idx, att);
    }
    // 3) Output projection: (65536x512) @ (512x512)^T + b -> (65536x512)
    {
        dim3 grid(DIM_ / 128, M / 128);
        sgemm_nt_bias<<<grid, 256>>>(att, proj_w, proj_b, out, M, DIM_, DIM_);
    }
}

// round 3
// speedup vs baseline: 1.5473x; 1.5473x over previous
#include <cuda_runtime.h>
#include <cuda_bf16.h>
#include <cstdint>

// Problem constants
#define BW_    1024
#define NTOK   64
#define DIM_   512
#define NH_    16
#define HD_    32
#define NW_    64
#define TRIPLE 1536
#define MTOT   (BW_ * NTOK)            /* 65536 */
#define SCALE_ 0.17677669529663687f

// ---------------------------------------------------------------------------
// Scratch (allocation-free rule: __device__ globals)
// ---------------------------------------------------------------------------
__device__ float         g_qkv[(size_t)MTOT * TRIPLE];      // fp32 qkv (~402MB)
__device__ __nv_bfloat16 g_xhi[(size_t)MTOT * DIM_];
__device__ __nv_bfloat16 g_xlo[(size_t)MTOT * DIM_];
__device__ __nv_bfloat16 g_ahi[(size_t)MTOT * DIM_];
__device__ __nv_bfloat16 g_alo[(size_t)MTOT * DIM_];
__device__ __nv_bfloat16 g_w1hi[TRIPLE * DIM_];
__device__ __nv_bfloat16 g_w1lo[TRIPLE * DIM_];
__device__ __nv_bfloat16 g_w2hi[DIM_ * DIM_];
__device__ __nv_bfloat16 g_w2lo[DIM_ * DIM_];

// ---------------------------------------------------------------------------
// helpers
// ---------------------------------------------------------------------------
__device__ __forceinline__ uint32_t smem_u32(const void* p) {
    uint32_t a;
    asm("{ .reg .u64 t; cvta.to.shared.u64 t, %1; cvt.u32.u64 %0, t; }"
        : "=r"(a) : "l"(p));
    return a;
}

#define CP_ASYNC16(smem_addr, gptr) \
    asm volatile("cp.async.cg.shared.global [%0], [%1], 16;" \
                 :: "r"((uint32_t)(smem_addr)), "l"(gptr) : "memory")
#define CP_ASYNC_COMMIT() asm volatile("cp.async.commit_group;" ::: "memory")
#define CP_ASYNC_WAIT0()  asm volatile("cp.async.wait_group 0;" ::: "memory")

__device__ __forceinline__ void ldsm4(uint32_t* r, uint32_t addr) {
    asm volatile("ldmatrix.sync.aligned.m8n8.x4.shared.b16 {%0,%1,%2,%3}, [%4];"
                 : "=r"(r[0]), "=r"(r[1]), "=r"(r[2]), "=r"(r[3]) : "r"(addr));
}

#define MMA_BF16(d, a, b0, b1) \
    asm volatile("mma.sync.aligned.m16n8k16.row.col.f32.bf16.bf16.f32 " \
        "{%0,%1,%2,%3}, {%4,%5,%6,%7}, {%8,%9}, {%0,%1,%2,%3};" \
        : "+f"((d)[0]), "+f"((d)[1]), "+f"((d)[2]), "+f"((d)[3]) \
        : "r"((a)[0]), "r"((a)[1]), "r"((a)[2]), "r"((a)[3]), "r"(b0), "r"(b1))

// ---------------------------------------------------------------------------
// fp32 -> (bf16 hi, bf16 lo) split
// ---------------------------------------------------------------------------
__global__ __launch_bounds__(256) void split_kernel(
    const float* __restrict__ in, __nv_bfloat16* __restrict__ hi,
    __nv_bfloat16* __restrict__ lo, int n)
{
    int i = (blockIdx.x * 256 + threadIdx.x) * 4;
    if (i >= n) return;
    float4 v = *(const float4*)(in + i);
    __nv_bfloat16 h[4], l[4];
    float vv[4] = {v.x, v.y, v.z, v.w};
    #pragma unroll
    for (int t = 0; t < 4; ++t) {
        h[t] = __float2bfloat16(vv[t]);
        l[t] = __float2bfloat16(vv[t] - __bfloat162float(h[t]));
    }
    *(uint2*)(hi + i) = *(uint2*)h;
    *(uint2*)(lo + i) = *(uint2*)l;
}

// ---------------------------------------------------------------------------
// Split-bf16 GEMM (NT) on mma.sync: C[m][n] = sum_k A[m][k]*B[n][k] + bias[n]
// CTA tile 128x128, BK=32, 256 threads (8 warps of 32x64), double-buffered
// cp.async. smem rows padded to 80B for conflict-free ldmatrix.
// ---------------------------------------------------------------------------
#define ROWB 80                      /* bytes per smem row (32 bf16 + 8 pad) */
#define TILE_B (128 * ROWB)          /* 10240 per tile */
#define STAGE_B (4 * TILE_B)         /* Ah, Al, Bh, Bl */

__global__ __launch_bounds__(256, 1)
void gemm_split(const __nv_bfloat16* __restrict__ Ahi,
                const __nv_bfloat16* __restrict__ Alo,
                const __nv_bfloat16* __restrict__ Bhi,
                const __nv_bfloat16* __restrict__ Blo,
                const float* __restrict__ bias, float* __restrict__ C,
                int Nn, int K)
{
    extern __shared__ char smem[];
    const uint32_t sbase = smem_u32(smem);

    const int tid  = threadIdx.x;
    const int lane = tid & 31;
    const int wid  = tid >> 5;
    const int wm   = (wid & 3) * 32;     // warp row offset in tile
    const int wn   = (wid >> 2) * 64;    // warp col offset in tile
    const int m0 = blockIdx.y * 128;
    const int n0 = blockIdx.x * 128;

    float acc[2][8][4];
    #pragma unroll
    for (int a = 0; a < 2; ++a)
        #pragma unroll
        for (int b = 0; b < 8; ++b)
            #pragma unroll
            for (int c = 0; c < 4; ++c) acc[a][b][c] = 0.f;

    const int nIter = K / 32;

    // ---- tile loader (stage s, k-offset k0) ----
    auto load_stage = [&](int s, int k0) {
        uint32_t st = sbase + s * STAGE_B;
        #pragma unroll
        for (int j = 0; j < 2; ++j) {
            int lin = tid + j * 256;        // 0..511
            int r = lin >> 2;               // 0..127
            int c = lin & 3;                // 16B chunk
            uint32_t dst = r * ROWB + c * 16;
            size_t ga = (size_t)(m0 + r) * K + k0 + c * 8;
            size_t gb = (size_t)(n0 + r) * K + k0 + c * 8;
            CP_ASYNC16(st + 0 * TILE_B + dst, Ahi + ga);
            CP_ASYNC16(st + 1 * TILE_B + dst, Alo + ga);
            CP_ASYNC16(st + 2 * TILE_B + dst, Bhi + gb);
            CP_ASYNC16(st + 3 * TILE_B + dst, Blo + gb);
        }
        CP_ASYNC_COMMIT();
    };

    load_stage(0, 0);

    // ldmatrix per-thread address components (constant across iters)
    const uint32_t a_row = wm + (lane & 15);
    const uint32_t a_k8  = (lane >> 4) * 8;           // bf16 col offset
    const int g = lane >> 3;
    const uint32_t b_row = wn + (g >> 1) * 8 + (lane & 7);
    const uint32_t b_k8  = (g & 1) * 8;

    for (int it = 0; it < nIter; ++it) {
        CP_ASYNC_WAIT0();
        __syncthreads();
        if (it + 1 < nIter) load_stage((it + 1) & 1, (it + 1) * 32);

        uint32_t st = sbase + (it & 1) * STAGE_B;
        uint32_t sAh = st, sAl = st + TILE_B, sBh = st + 2 * TILE_B,
                 sBl = st + 3 * TILE_B;

        #pragma unroll
        for (int ks = 0; ks < 2; ++ks) {
            uint32_t ah[2][4], al[2][4], bh[4][4], bl[4][4];
            uint32_t akoff = (ks * 16 + a_k8) * 2;
            uint32_t bkoff = (ks * 16 + b_k8) * 2;
            #pragma unroll
            for (int mt = 0; mt < 2; ++mt) {
                uint32_t off = (a_row + mt * 16) * ROWB + akoff;
                ldsm4(ah[mt], sAh + off);
                ldsm4(al[mt], sAl + off);
            }
            #pragma unroll
            for (int nt = 0; nt < 4; ++nt) {
                uint32_t off = (b_row + nt * 16) * ROWB + bkoff;
                ldsm4(bh[nt], sBh + off);
                ldsm4(bl[nt], sBl + off);
            }
            #pragma unroll
            for (int mt = 0; mt < 2; ++mt)
                #pragma unroll
                for (int nt = 0; nt < 8; ++nt) {
                    int q = nt >> 1, h = (nt & 1) * 2;
                    MMA_BF16(acc[mt][nt], ah[mt], bh[q][h], bh[q][h + 1]);
                }
            #pragma unroll
            for (int mt = 0; mt < 2; ++mt)
                #pragma unroll
                for (int nt = 0; nt < 8; ++nt) {
                    int q = nt >> 1, h = (nt & 1) * 2;
                    MMA_BF16(acc[mt][nt], ah[mt], bl[q][h], bl[q][h + 1]);
                }
            #pragma unroll
            for (int mt = 0; mt < 2; ++mt)
                #pragma unroll
                for (int nt = 0; nt < 8; ++nt) {
                    int q = nt >> 1, h = (nt & 1) * 2;
                    MMA_BF16(acc[mt][nt], al[mt], bh[q][h], bh[q][h + 1]);
                }
        }
        __syncthreads();
    }

    // Epilogue: scatter accumulators + bias
    #pragma unroll
    for (int mt = 0; mt < 2; ++mt) {
        int r0 = m0 + wm + mt * 16 + (lane >> 2);
        #pragma unroll
        for (int nt = 0; nt < 8; ++nt) {
            int col = n0 + wn + (nt >> 1) * 16 + (nt & 1) * 8 + (lane & 3) * 2;
            float b0 = __ldg(bias + col), b1 = __ldg(bias + col + 1);
            float2 v0 = {acc[mt][nt][0] + b0, acc[mt][nt][1] + b1};
            float2 v1 = {acc[mt][nt][2] + b0, acc[mt][nt][3] + b1};
            *(float2*)(C + (size_t)r0 * Nn + col) = v0;
            *(float2*)(C + (size_t)(r0 + 8) * Nn + col) = v1;
        }
    }
}

// ---------------------------------------------------------------------------
// Attention: one block per (head, window). 128 threads. fp32 math.
// Emits bf16 hi/lo split directly for the proj GEMM.
// ---------------------------------------------------------------------------
__global__ __launch_bounds__(128) void attn_kernel(
    const float* __restrict__ qkv,        // (BW, N, 1536)
    const float* __restrict__ mask,       // (NW, N, N)
    const float* __restrict__ table,      // (225, NH)
    const int*   __restrict__ rel_index,  // (N, N)
    __nv_bfloat16* __restrict__ outhi,
    __nv_bfloat16* __restrict__ outlo)
{
    const int h  = blockIdx.x;
    const int bw = blockIdx.y;
    const int tid = threadIdx.x;

    __shared__ float q[64][33];
    __shared__ float k[64][33];
    __shared__ float v[64][33];
    __shared__ float s[64][65];

    const float* base = qkv + (size_t)bw * NTOK * TRIPLE + h * HD_;
    #pragma unroll
    for (int r = 0; r < 16; ++r) {
        int lin = tid + r * 128;
        int n = lin >> 5, d = lin & 31;
        q[n][d] = base[n * TRIPLE + d] * SCALE_;
        k[n][d] = base[n * TRIPLE + 512 + d];
        v[n][d] = base[n * TRIPLE + 1024 + d];
    }
    __syncthreads();

    const float* mrow = mask + (size_t)(bw & (NW_ - 1)) * (NTOK * NTOK);
    const int i = tid >> 1;
    const int jbase = (tid & 1) * 32;
    #pragma unroll 4
    for (int jj = 0; jj < 32; ++jj) {
        int j = jbase + jj;
        float a = 0.f;
        #pragma unroll
        for (int d = 0; d < 32; ++d) a += q[i][d] * k[j][d];
        a += table[rel_index[i * 64 + j] * NH_ + h] + mrow[i * 64 + j];
        s[i][j] = a;
    }
    __syncthreads();

    const int warp = tid >> 5, lane = tid & 31;
    for (int rr = 0; rr < 16; ++rr) {
        int row = warp * 16 + rr;
        float a0 = s[row][lane], a1 = s[row][lane + 32];
        float m = fmaxf(a0, a1);
        #pragma unroll
        for (int o = 16; o > 0; o >>= 1) m = fmaxf(m, __shfl_xor_sync(0xffffffffu, m, o));
        float e0 = __expf(a0 - m), e1 = __expf(a1 - m);
        float sm = e0 + e1;
        #pragma unroll
        for (int o = 16; o > 0; o >>= 1) sm += __shfl_xor_sync(0xffffffffu, sm, o);
        float inv = 1.f / sm;
        s[row][lane] = e0 * inv;
        s[row][lane + 32] = e1 * inv;
    }
    __syncthreads();

    const int dbase = (tid & 1) * 16;
    float acc[16];
    #pragma unroll
    for (int t = 0; t < 16; ++t) acc[t] = 0.f;
    #pragma unroll 4
    for (int j = 0; j < 64; ++j) {
        float p = s[i][j];
        #pragma unroll
        for (int t = 0; t < 16; ++t) acc[t] += p * v[j][dbase + t];
    }
    size_t obase = (size_t)bw * NTOK * DIM_ + (size_t)i * DIM_ + h * HD_ + dbase;
    #pragma unroll
    for (int t = 0; t < 16; ++t) {
        __nv_bfloat16 hi = __float2bfloat16(acc[t]);
        __nv_bfloat16 lo = __float2bfloat16(acc[t] - __bfloat162float(hi));
        outhi[obase + t] = hi;
        outlo[obase + t] = lo;
    }
}

// ---------------------------------------------------------------------------
extern "C" void kernel_launch(void* const* d_in, const int* in_sizes, int n_in,
                              void* d_out, int out_size)
{
    const float* x       = (const float*)d_in[0];
    const float* mask    = (const float*)d_in[1];
    const float* qkv_w   = (const float*)d_in[2];
    const float* qkv_b   = (const float*)d_in[3];
    const float* table   = (const float*)d_in[4];
    const float* proj_w  = (const float*)d_in[5];
    const float* proj_b  = (const float*)d_in[6];
    const int*   rel_idx = (const int*)d_in[7];
    float* out = (float*)d_out;

    float *qkv;
    __nv_bfloat16 *xhi, *xlo, *ahi, *alo, *w1hi, *w1lo, *w2hi, *w2lo;
    cudaGetSymbolAddress((void**)&qkv, g_qkv);
    cudaGetSymbolAddress((void**)&xhi, g_xhi);
    cudaGetSymbolAddress((void**)&xlo, g_xlo);
    cudaGetSymbolAddress((void**)&ahi, g_ahi);
    cudaGetSymbolAddress((void**)&alo, g_alo);
    cudaGetSymbolAddress((void**)&w1hi, g_w1hi);
    cudaGetSymbolAddress((void**)&w1lo, g_w1lo);
    cudaGetSymbolAddress((void**)&w2hi, g_w2hi);
    cudaGetSymbolAddress((void**)&w2lo, g_w2lo);

    const int gemm_smem = 2 * STAGE_B;   // 81920
    cudaFuncSetAttribute(gemm_split, cudaFuncAttributeMaxDynamicSharedMemorySize,
                         gemm_smem);

    // 1) splits
    {
        int n1 = MTOT * DIM_;
        split_kernel<<<n1 / 4 / 256, 256>>>(x, xhi, xlo, n1);
        int n2 = TRIPLE * DIM_;
        split_kernel<<<n2 / 4 / 256, 256>>>(qkv_w, w1hi, w1lo, n2);
        int n3 = DIM_ * DIM_;
        split_kernel<<<n3 / 4 / 256, 256>>>(proj_w, w2hi, w2lo, n3);
    }
    // 2) QKV GEMM: (65536x512)@(1536x512)^T + b
    {
        dim3 grid(TRIPLE / 128, MTOT / 128);
        gemm_split<<<grid, 256, gemm_smem>>>(xhi, xlo, w1hi, w1lo, qkv_b, qkv,
                                             TRIPLE, DIM_);
    }
    // 3) attention
    {
        dim3 grid(NH_, BW_);
        attn_kernel<<<grid, 128>>>(qkv, mask, table, rel_idx, ahi, alo);
    }
    // 4) proj GEMM: (65536x512)@(512x512)^T + b
    {
        dim3 grid(DIM_ / 128, MTOT / 128);
        gemm_split<<<grid, 256, gemm_smem>>>(ahi, alo, w2hi, w2lo, proj_b, out,
                                             DIM_, DIM_);
    }
}

// round 4
// speedup vs baseline: 2.6728x; 1.7274x over previous
#include <cuda_runtime.h>
#include <cuda_fp16.h>
#include <cstdint>

// Problem constants
#define BW_    1024
#define NTOK   64
#define DIM_   512
#define NH_    16
#define HD_    32
#define NW_    64
#define TRIPLE 1536
#define MTOT   (BW_ * NTOK)            /* 65536 */
#define SCALE_ 0.17677669529663687f

// ---------------------------------------------------------------------------
// Scratch (allocation-free rule: __device__ globals)
// ---------------------------------------------------------------------------
__device__ float  g_qkv[(size_t)MTOT * TRIPLE];     // fp32 qkv (~402MB)
__device__ __half g_xh[(size_t)MTOT * DIM_];        // x in fp16
__device__ __half g_ah[(size_t)MTOT * DIM_];        // attn out fp16
__device__ __half g_w1h[TRIPLE * DIM_];
__device__ __half g_w2h[DIM_ * DIM_];

// ---------------------------------------------------------------------------
// helpers
// ---------------------------------------------------------------------------
__device__ __forceinline__ uint32_t smem_u32(const void* p) {
    uint32_t a;
    asm("{ .reg .u64 t; cvta.to.shared.u64 t, %1; cvt.u32.u64 %0, t; }"
        : "=r"(a) : "l"(p));
    return a;
}

#define CP_ASYNC16(smem_addr, gptr) \
    asm volatile("cp.async.cg.shared.global [%0], [%1], 16;" \
                 :: "r"((uint32_t)(smem_addr)), "l"(gptr) : "memory")
#define CP_ASYNC_COMMIT() asm volatile("cp.async.commit_group;" ::: "memory")
#define CP_ASYNC_WAIT0()  asm volatile("cp.async.wait_group 0;" ::: "memory")
#define CP_ASYNC_WAIT1()  asm volatile("cp.async.wait_group 1;" ::: "memory")

__device__ __forceinline__ void ldsm4(uint32_t* r, uint32_t addr) {
    asm volatile("ldmatrix.sync.aligned.m8n8.x4.shared.b16 {%0,%1,%2,%3}, [%4];"
                 : "=r"(r[0]), "=r"(r[1]), "=r"(r[2]), "=r"(r[3]) : "r"(addr));
}

#define MMA_F16(d, a, b0, b1) \
    asm volatile("mma.sync.aligned.m16n8k16.row.col.f32.f16.f16.f32 " \
        "{%0,%1,%2,%3}, {%4,%5,%6,%7}, {%8,%9}, {%0,%1,%2,%3};" \
        : "+f"((d)[0]), "+f"((d)[1]), "+f"((d)[2]), "+f"((d)[3]) \
        : "r"((a)[0]), "r"((a)[1]), "r"((a)[2]), "r"((a)[3]), "r"(b0), "r"(b1))

// ---------------------------------------------------------------------------
// fp32 -> fp16 convert
// ---------------------------------------------------------------------------
__global__ __launch_bounds__(256) void convert_half(
    const float* __restrict__ in, __half* __restrict__ out, int n)
{
    int i = (blockIdx.x * 256 + threadIdx.x) * 4;
    if (i >= n) return;
    float4 v = *(const float4*)(in + i);
    __half h[4] = {__float2half(v.x), __float2half(v.y),
                   __float2half(v.z), __float2half(v.w)};
    *(uint2*)(out + i) = *(uint2*)h;
}

// ---------------------------------------------------------------------------
// fp16 GEMM (NT) on mma.sync: C[m][n] = sum_k A[m][k]*B[n][k] + bias[n]
// CTA tile 128x128, BK=32, 256 threads (8 warps of 32x64), 3-stage cp.async.
// smem rows padded to 80B for conflict-free ldmatrix.
// ---------------------------------------------------------------------------
#define ROWB 80                      /* bytes per smem row (32 half + 8 pad) */
#define TILE_B (128 * ROWB)          /* 10240 per tile */
#define STAGE_B (2 * TILE_B)         /* A, B */
#define NSTAGE 3

__global__ __launch_bounds__(256, 2)
void gemm_h(const __half* __restrict__ A, const __half* __restrict__ B,
            const float* __restrict__ bias, float* __restrict__ C,
            int Nn, int K)
{
    extern __shared__ char smem[];
    const uint32_t sbase = smem_u32(smem);

    const int tid  = threadIdx.x;
    const int lane = tid & 31;
    const int wid  = tid >> 5;
    const int wm   = (wid & 3) * 32;
    const int wn   = (wid >> 2) * 64;
    const int m0 = blockIdx.y * 128;
    const int n0 = blockIdx.x * 128;

    float acc[2][8][4];
    #pragma unroll
    for (int a = 0; a < 2; ++a)
        #pragma unroll
        for (int b = 0; b < 8; ++b)
            #pragma unroll
            for (int c = 0; c < 4; ++c) acc[a][b][c] = 0.f;

    const int nIter = K / 32;

    auto load_stage = [&](int s, int k0) {
        uint32_t st = sbase + s * STAGE_B;
        #pragma unroll
        for (int j = 0; j < 2; ++j) {
            int lin = tid + j * 256;        // 0..511
            int r = lin >> 2;               // 0..127
            int c = lin & 3;                // 16B chunk
            uint32_t dst = r * ROWB + c * 16;
            CP_ASYNC16(st + dst, A + (size_t)(m0 + r) * K + k0 + c * 8);
            CP_ASYNC16(st + TILE_B + dst, B + (size_t)(n0 + r) * K + k0 + c * 8);
        }
        CP_ASYNC_COMMIT();
    };

    load_stage(0, 0);
    load_stage(1, 32);

    const uint32_t a_row = wm + (lane & 15);
    const uint32_t a_k8  = (lane >> 4) * 8;
    const int g = lane >> 3;
    const uint32_t b_row = wn + (g >> 1) * 8 + (lane & 7);
    const uint32_t b_k8  = (g & 1) * 8;

    for (int it = 0; it < nIter; ++it) {
        if (it + 1 < nIter) { CP_ASYNC_WAIT1(); } else { CP_ASYNC_WAIT0(); }
        __syncthreads();
        if (it + 2 < nIter) load_stage((it + 2) % NSTAGE, (it + 2) * 32);

        uint32_t st = sbase + (it % NSTAGE) * STAGE_B;
        uint32_t sA = st, sB = st + TILE_B;

        #pragma unroll
        for (int ks = 0; ks < 2; ++ks) {
            uint32_t ah[2][4], bh[4][4];
            uint32_t akoff = (ks * 16 + a_k8) * 2;
            uint32_t bkoff = (ks * 16 + b_k8) * 2;
            #pragma unroll
            for (int mt = 0; mt < 2; ++mt)
                ldsm4(ah[mt], sA + (a_row + mt * 16) * ROWB + akoff);
            #pragma unroll
            for (int nt = 0; nt < 4; ++nt)
                ldsm4(bh[nt], sB + (b_row + nt * 16) * ROWB + bkoff);
            #pragma unroll
            for (int mt = 0; mt < 2; ++mt)
                #pragma unroll
                for (int nt = 0; nt < 8; ++nt) {
                    int q = nt >> 1, h = (nt & 1) * 2;
                    MMA_F16(acc[mt][nt], ah[mt], bh[q][h], bh[q][h + 1]);
                }
        }
        __syncthreads();
    }

    // Epilogue: scatter accumulators + bias
    #pragma unroll
    for (int mt = 0; mt < 2; ++mt) {
        int r0 = m0 + wm + mt * 16 + (lane >> 2);
        #pragma unroll
        for (int nt = 0; nt < 8; ++nt) {
            int col = n0 + wn + (nt >> 1) * 16 + (nt & 1) * 8 + (lane & 3) * 2;
            float b0 = __ldg(bias + col), b1 = __ldg(bias + col + 1);
            float2 v0 = {acc[mt][nt][0] + b0, acc[mt][nt][1] + b1};
            float2 v1 = {acc[mt][nt][2] + b0, acc[mt][nt][3] + b1};
            *(float2*)(C + (size_t)r0 * Nn + col) = v0;
            *(float2*)(C + (size_t)(r0 + 8) * Nn + col) = v1;
        }
    }
}

// ---------------------------------------------------------------------------
// Attention: one block per (head, window). 128 threads. fp32 math.
// Emits fp16 output for the proj GEMM.
// ---------------------------------------------------------------------------
__global__ __launch_bounds__(128) void attn_kernel(
    const float* __restrict__ qkv,        // (BW, N, 1536)
    const float* __restrict__ mask,       // (NW, N, N)
    const float* __restrict__ table,      // (225, NH)
    const int*   __restrict__ rel_index,  // (N, N)
    __half* __restrict__ outh)            // (BW, N, DIM)
{
    const int h  = blockIdx.x;
    const int bw = blockIdx.y;
    const int tid = threadIdx.x;

    __shared__ float q[64][33];
    __shared__ float k[64][33];
    __shared__ float v[64][33];
    __shared__ float s[64][65];

    const float* base = qkv + (size_t)bw * NTOK * TRIPLE + h * HD_;
    #pragma unroll
    for (int r = 0; r < 16; ++r) {
        int lin = tid + r * 128;
        int n = lin >> 5, d = lin & 31;
        q[n][d] = base[n * TRIPLE + d] * SCALE_;
        k[n][d] = base[n * TRIPLE + 512 + d];
        v[n][d] = base[n * TRIPLE + 1024 + d];
    }
    __syncthreads();

    const float* mrow = mask + (size_t)(bw & (NW_ - 1)) * (NTOK * NTOK);
    const int i = tid >> 1;
    const int jbase = (tid & 1) * 32;
    #pragma unroll 4
    for (int jj = 0; jj < 32; ++jj) {
        int j = jbase + jj;
        float a = 0.f;
        #pragma unroll
        for (int d = 0; d < 32; ++d) a += q[i][d] * k[j][d];
        a += table[rel_index[i * 64 + j] * NH_ + h] + mrow[i * 64 + j];
        s[i][j] = a;
    }
    __syncthreads();

    const int warp = tid >> 5, lane = tid & 31;
    for (int rr = 0; rr < 16; ++rr) {
        int row = warp * 16 + rr;
        float a0 = s[row][lane], a1 = s[row][lane + 32];
        float m = fmaxf(a0, a1);
        #pragma unroll
        for (int o = 16; o > 0; o >>= 1) m = fmaxf(m, __shfl_xor_sync(0xffffffffu, m, o));
        float e0 = __expf(a0 - m), e1 = __expf(a1 - m);
        float sm = e0 + e1;
        #pragma unroll
        for (int o = 16; o > 0; o >>= 1) sm += __shfl_xor_sync(0xffffffffu, sm, o);
        float inv = 1.f / sm;
        s[row][lane] = e0 * inv;
        s[row][lane + 32] = e1 * inv;
    }
    __syncthreads();

    const int dbase = (tid & 1) * 16;
    float acc[16];
    #pragma unroll
    for (int t = 0; t < 16; ++t) acc[t] = 0.f;
    #pragma unroll 4
    for (int j = 0; j < 64; ++j) {
        float p = s[i][j];
        #pragma unroll
        for (int t = 0; t < 16; ++t) acc[t] += p * v[j][dbase + t];
    }
    size_t obase = (size_t)bw * NTOK * DIM_ + (size_t)i * DIM_ + h * HD_ + dbase;
    __half hv[16];
    #pragma unroll
    for (int t = 0; t < 16; ++t) hv[t] = __float2half(acc[t]);
    #pragma unroll
    for (int t = 0; t < 16; t += 4)
        *(uint2*)(outh + obase + t) = *(uint2*)(hv + t);
}

// ---------------------------------------------------------------------------
extern "C" void kernel_launch(void* const* d_in, const int* in_sizes, int n_in,
                              void* d_out, int out_size)
{
    const float* x       = (const float*)d_in[0];
    const float* mask    = (const float*)d_in[1];
    const float* qkv_w   = (const float*)d_in[2];
    const float* qkv_b   = (const float*)d_in[3];
    const float* table   = (const float*)d_in[4];
    const float* proj_w  = (const float*)d_in[5];
    const float* proj_b  = (const float*)d_in[6];
    const int*   rel_idx = (const int*)d_in[7];
    float* out = (float*)d_out;

    float *qkv;
    __half *xh, *ah, *w1h, *w2h;
    cudaGetSymbolAddress((void**)&qkv, g_qkv);
    cudaGetSymbolAddress((void**)&xh, g_xh);
    cudaGetSymbolAddress((void**)&ah, g_ah);
    cudaGetSymbolAddress((void**)&w1h, g_w1h);
    cudaGetSymbolAddress((void**)&w2h, g_w2h);

    const int gemm_smem = NSTAGE * STAGE_B;   // 61440
    cudaFuncSetAttribute(gemm_h, cudaFuncAttributeMaxDynamicSharedMemorySize,
                         gemm_smem);

    // 1) fp16 conversions
    {
        int n1 = MTOT * DIM_;
        convert_half<<<n1 / 4 / 256, 256>>>(x, xh, n1);
        int n2 = TRIPLE * DIM_;
        convert_half<<<n2 / 4 / 256, 256>>>(qkv_w, w1h, n2);
        int n3 = DIM_ * DIM_;
        convert_half<<<n3 / 4 / 256, 256>>>(proj_w, w2h, n3);
    }
    // 2) QKV GEMM: (65536x512)@(1536x512)^T + b -> fp32 qkv
    {
        dim3 grid(TRIPLE / 128, MTOT / 128);
        gemm_h<<<grid, 256, gemm_smem>>>(xh, w1h, qkv_b, qkv, TRIPLE, DIM_);
    }
    // 3) attention (fp32 in, fp16 out)
    {
        dim3 grid(NH_, BW_);
        attn_kernel<<<grid, 128>>>(qkv, mask, table, rel_idx, ah);
    }
    // 4) proj GEMM: (65536x512)@(512x512)^T + b -> fp32 out
    {
        dim3 grid(DIM_ / 128, MTOT / 128);
        gemm_h<<<grid, 256, gemm_smem>>>(ah, w2h, proj_b, out, DIM_, DIM_);
    }
}

// round 6
// speedup vs baseline: 6.7012x; 2.5072x over previous
#include <cuda_runtime.h>
#include <cuda_fp16.h>
#include <cstdint>

// Problem constants
#define BW_    1024
#define NTOK   64
#define DIM_   512
#define NH_    16
#define HD_    32
#define NW_    64
#define TRIPLE 1536
#define MTOT   (BW_ * NTOK)            /* 65536 */
#define SCALE_ 0.17677669529663687f

// ---------------------------------------------------------------------------
// Scratch (allocation-free rule: __device__ globals)
// ---------------------------------------------------------------------------
__device__ __half g_qkvh[(size_t)MTOT * TRIPLE];    // fp16 qkv (~201MB)
__device__ __half g_xh[(size_t)MTOT * DIM_];
__device__ __half g_ah[(size_t)MTOT * DIM_];
__device__ __half g_w1h[TRIPLE * DIM_];
__device__ __half g_w2h[DIM_ * DIM_];
__device__ float  g_b1[TRIPLE];                      // prescaled qkv bias
__device__ float  g_bias[NH_ * NTOK * NTOK];         // gathered rel bias

// ---------------------------------------------------------------------------
// helpers
// ---------------------------------------------------------------------------
__device__ __forceinline__ uint32_t smem_u32(const void* p) {
    uint32_t a;
    asm("{ .reg .u64 t; cvta.to.shared.u64 t, %1; cvt.u32.u64 %0, t; }"
        : "=r"(a) : "l"(p));
    return a;
}

#define CP_ASYNC16(smem_addr, gptr) \
    asm volatile("cp.async.cg.shared.global [%0], [%1], 16;" \
                 :: "r"((uint32_t)(smem_addr)), "l"(gptr) : "memory")
#define CP_ASYNC_COMMIT() asm volatile("cp.async.commit_group;" ::: "memory")
#define CP_ASYNC_WAIT0()  asm volatile("cp.async.wait_group 0;" ::: "memory")
#define CP_ASYNC_WAIT1()  asm volatile("cp.async.wait_group 1;" ::: "memory")

__device__ __forceinline__ void ldsm4(uint32_t* r, uint32_t addr) {
    asm volatile("ldmatrix.sync.aligned.m8n8.x4.shared.b16 {%0,%1,%2,%3}, [%4];"
                 : "=r"(r[0]), "=r"(r[1]), "=r"(r[2]), "=r"(r[3]) : "r"(addr));
}
__device__ __forceinline__ void ldsm4t(uint32_t* r, uint32_t addr) {
    asm volatile("ldmatrix.sync.aligned.m8n8.x4.trans.shared.b16 {%0,%1,%2,%3}, [%4];"
                 : "=r"(r[0]), "=r"(r[1]), "=r"(r[2]), "=r"(r[3]) : "r"(addr));
}

#define MMA_F16(d, a0, a1, a2, a3, b0, b1) \
    asm volatile("mma.sync.aligned.m16n8k16.row.col.f32.f16.f16.f32 " \
        "{%0,%1,%2,%3}, {%4,%5,%6,%7}, {%8,%9}, {%0,%1,%2,%3};" \
        : "+f"((d)[0]), "+f"((d)[1]), "+f"((d)[2]), "+f"((d)[3]) \
        : "r"(a0), "r"(a1), "r"(a2), "r"(a3), "r"(b0), "r"(b1))

// ---------------------------------------------------------------------------
// Prep kernels
// ---------------------------------------------------------------------------
__global__ __launch_bounds__(256) void convert_half(
    const float* __restrict__ in, __half* __restrict__ out, int n)
{
    int i = (blockIdx.x * 256 + threadIdx.x) * 4;
    if (i >= n) return;
    float4 v = *(const float4*)(in + i);
    __half h[4] = {__float2half(v.x), __float2half(v.y),
                   __float2half(v.z), __float2half(v.w)};
    *(uint2*)(out + i) = *(uint2*)h;
}

// qkv weight with Wq rows scaled by SCALE_
__global__ __launch_bounds__(256) void convert_w1(
    const float* __restrict__ in, __half* __restrict__ out)
{
    int i = (blockIdx.x * 256 + threadIdx.x) * 4;
    float sc = (i < 512 * 512) ? SCALE_ : 1.0f;
    float4 v = *(const float4*)(in + i);
    __half h[4] = {__float2half(v.x * sc), __float2half(v.y * sc),
                   __float2half(v.z * sc), __float2half(v.w * sc)};
    *(uint2*)(out + i) = *(uint2*)h;
}

__global__ __launch_bounds__(256) void prep_misc(
    const float* __restrict__ qkv_b, float* __restrict__ b1,
    const float* __restrict__ table, const int* __restrict__ rel_index,
    float* __restrict__ bias)
{
    int idx = blockIdx.x * 256 + threadIdx.x;
    if (idx < TRIPLE)
        b1[idx] = qkv_b[idx] * (idx < 512 ? SCALE_ : 1.0f);
    // bias gather: 16 heads x 4096
    for (int t = idx; t < NH_ * NTOK * NTOK; t += gridDim.x * 256) {
        int h = t >> 12, ij = t & 4095;
        bias[t] = table[rel_index[ij] * NH_ + h];
    }
}

// ---------------------------------------------------------------------------
// fp16 GEMM (NT) on mma.sync: C = A @ B^T + bias. Templated output type.
// CTA 128x128, BK=32, 256 thr (8 warps of 32x64), 3-stage cp.async.
// ---------------------------------------------------------------------------
#define ROWB 80
#define TILE_B (128 * ROWB)
#define STAGE_B (2 * TILE_B)
#define NSTAGE 3

template <typename OutT>
__global__ __launch_bounds__(256, 2)
void gemm_h(const __half* __restrict__ A, const __half* __restrict__ B,
            const float* __restrict__ bias, OutT* __restrict__ C,
            int Nn, int K)
{
    extern __shared__ char smem[];
    const uint32_t sbase = smem_u32(smem);

    const int tid  = threadIdx.x;
    const int lane = tid & 31;
    const int wid  = tid >> 5;
    const int wm   = (wid & 3) * 32;
    const int wn   = (wid >> 2) * 64;
    const int m0 = blockIdx.y * 128;
    const int n0 = blockIdx.x * 128;

    float acc[2][8][4];
    #pragma unroll
    for (int a = 0; a < 2; ++a)
        #pragma unroll
        for (int b = 0; b < 8; ++b)
            #pragma unroll
            for (int c = 0; c < 4; ++c) acc[a][b][c] = 0.f;

    const int nIter = K / 32;

    auto load_stage = [&](int s, int k0) {
        uint32_t st = sbase + s * STAGE_B;
        #pragma unroll
        for (int j = 0; j < 2; ++j) {
            int lin = tid + j * 256;
            int r = lin >> 2;
            int c = lin & 3;
            uint32_t dst = r * ROWB + c * 16;
            CP_ASYNC16(st + dst, A + (size_t)(m0 + r) * K + k0 + c * 8);
            CP_ASYNC16(st + TILE_B + dst, B + (size_t)(n0 + r) * K + k0 + c * 8);
        }
        CP_ASYNC_COMMIT();
    };

    load_stage(0, 0);
    load_stage(1, 32);

    const uint32_t a_row = wm + (lane & 15);
    const uint32_t a_k8  = (lane >> 4) * 8;
    const int g = lane >> 3;
    const uint32_t b_row = wn + (g >> 1) * 8 + (lane & 7);
    const uint32_t b_k8  = (g & 1) * 8;

    for (int it = 0; it < nIter; ++it) {
        if (it + 1 < nIter) { CP_ASYNC_WAIT1(); } else { CP_ASYNC_WAIT0(); }
        __syncthreads();
        if (it + 2 < nIter) load_stage((it + 2) % NSTAGE, (it + 2) * 32);

        uint32_t st = sbase + (it % NSTAGE) * STAGE_B;
        uint32_t sA = st, sB = st + TILE_B;

        #pragma unroll
        for (int ks = 0; ks < 2; ++ks) {
            uint32_t ah[2][4], bh[4][4];
            uint32_t akoff = (ks * 16 + a_k8) * 2;
            uint32_t bkoff = (ks * 16 + b_k8) * 2;
            #pragma unroll
            for (int mt = 0; mt < 2; ++mt)
                ldsm4(ah[mt], sA + (a_row + mt * 16) * ROWB + akoff);
            #pragma unroll
            for (int nt = 0; nt < 4; ++nt)
                ldsm4(bh[nt], sB + (b_row + nt * 16) * ROWB + bkoff);
            #pragma unroll
            for (int mt = 0; mt < 2; ++mt)
                #pragma unroll
                for (int nt = 0; nt < 8; ++nt) {
                    int q = nt >> 1, h = (nt & 1) * 2;
                    MMA_F16(acc[mt][nt], ah[mt][0], ah[mt][1], ah[mt][2],
                            ah[mt][3], bh[q][h], bh[q][h + 1]);
                }
        }
        __syncthreads();
    }

    #pragma unroll
    for (int mt = 0; mt < 2; ++mt) {
        int r0 = m0 + wm + mt * 16 + (lane >> 2);
        #pragma unroll
        for (int nt = 0; nt < 8; ++nt) {
            int col = n0 + wn + (nt >> 1) * 16 + (nt & 1) * 8 + (lane & 3) * 2;
            float b0 = __ldg(bias + col), b1 = __ldg(bias + col + 1);
            float v00 = acc[mt][nt][0] + b0, v01 = acc[mt][nt][1] + b1;
            float v10 = acc[mt][nt][2] + b0, v11 = acc[mt][nt][3] + b1;
            if (sizeof(OutT) == 2) {
                __half2 h0 = __floats2half2_rn(v00, v01);
                __half2 h1 = __floats2half2_rn(v10, v11);
                *(__half2*)((__half*)C + (size_t)r0 * Nn + col) = h0;
                *(__half2*)((__half*)C + (size_t)(r0 + 8) * Nn + col) = h1;
            } else {
                float2 f0 = {v00, v01}, f1 = {v10, v11};
                *(float2*)((float*)C + (size_t)r0 * Nn + col) = f0;
                *(float2*)((float*)C + (size_t)(r0 + 8) * Nn + col) = f1;
            }
        }
    }
}

// ---------------------------------------------------------------------------
// Attention via mma.sync: one block per (head, window), 4 warps.
// Warp w owns rows 16w..16w+15. S = Q@K^T (+bias+mask), softmax, O = P@V.
// ---------------------------------------------------------------------------
#define AROWB 80   /* 32 halfs + pad */

__global__ __launch_bounds__(128) void attn_mma(
    const __half* __restrict__ qkv,      // (BW, N, 1536), Wq prescaled
    const float* __restrict__ mask,      // (NW, 64, 64)
    const float* __restrict__ bias,      // (NH, 64, 64)
    __half* __restrict__ outh)           // (BW, N, DIM)
{
    const int h  = blockIdx.x;
    const int bw = blockIdx.y;
    const int tid = threadIdx.x;
    const int lane = tid & 31;
    const int wid = tid >> 5;

    __shared__ __align__(16) unsigned char sm[3 * 64 * AROWB];
    const uint32_t sbase = smem_u32(sm);
    const uint32_t sQ = sbase, sK = sbase + 64 * AROWB, sV = sbase + 2 * 64 * AROWB;

    // Load Q,K,V tiles (64x32 fp16 each) into padded smem.
    {
        const __half* src = qkv + (size_t)bw * NTOK * TRIPLE + h * HD_;
        #pragma unroll
        for (int t = 0; t < 6; ++t) {
            int lin = tid + t * 128;          // 0..767
            int m = lin >> 8;                 // 0=q 1=k 2=v
            int rem = lin & 255;
            int row = rem >> 2, c16 = rem & 3;
            uint4 val = *(const uint4*)(src + (size_t)row * TRIPLE + m * 512 + c16 * 8);
            *(uint4*)(sm + m * 64 * AROWB + row * AROWB + c16 * 16) = val;
        }
    }
    __syncthreads();

    // ---- Phase 1: S = Q @ K^T  (warp rows 16w..16w+15, cols 0..63) ----
    float s[8][4];
    #pragma unroll
    for (int nt = 0; nt < 8; ++nt)
        #pragma unroll
        for (int c = 0; c < 4; ++c) s[nt][c] = 0.f;

    const uint32_t a_row = wid * 16 + (lane & 15);
    const uint32_t a_k8  = (lane >> 4) * 8;
    const int g = lane >> 3;
    const uint32_t b_row = (g >> 1) * 8 + (lane & 7);
    const uint32_t b_k8  = (g & 1) * 8;

    #pragma unroll
    for (int ks = 0; ks < 2; ++ks) {
        uint32_t aq[4], bk[4][4];
        uint32_t akoff = (ks * 16 + a_k8) * 2;
        uint32_t bkoff = (ks * 16 + b_k8) * 2;
        ldsm4(aq, sQ + a_row * AROWB + akoff);
        #pragma unroll
        for (int nt = 0; nt < 4; ++nt)
            ldsm4(bk[nt], sK + (b_row + nt * 16) * AROWB + bkoff);
        #pragma unroll
        for (int nt = 0; nt < 8; ++nt) {
            int q = nt >> 1, hh = (nt & 1) * 2;
            MMA_F16(s[nt], aq[0], aq[1], aq[2], aq[3], bk[q][hh], bk[q][hh + 1]);
        }
    }

    // ---- bias + mask ----
    const int r = wid * 16 + (lane >> 2);
    const int cbase = (lane & 3) * 2;
    const float* brow = bias + ((size_t)h << 12);
    const float* mrow = mask + ((size_t)(bw & (NW_ - 1)) << 12);
    #pragma unroll
    for (int nt = 0; nt < 8; ++nt) {
        int c = nt * 8 + cbase;
        float2 b0 = *(const float2*)(brow + r * 64 + c);
        float2 m0 = *(const float2*)(mrow + r * 64 + c);
        float2 b1 = *(const float2*)(brow + (r + 8) * 64 + c);
        float2 m1 = *(const float2*)(mrow + (r + 8) * 64 + c);
        s[nt][0] += b0.x + m0.x; s[nt][1] += b0.y + m0.y;
        s[nt][2] += b1.x + m1.x; s[nt][3] += b1.y + m1.y;
    }

    // ---- softmax over 64 cols, rows r and r+8 (4 lanes per row) ----
    {
        float mx0 = -1e30f, mx1 = -1e30f;
        #pragma unroll
        for (int nt = 0; nt < 8; ++nt) {
            mx0 = fmaxf(mx0, fmaxf(s[nt][0], s[nt][1]));
            mx1 = fmaxf(mx1, fmaxf(s[nt][2], s[nt][3]));
        }
        #pragma unroll
        for (int o = 1; o <= 2; o <<= 1) {
            mx0 = fmaxf(mx0, __shfl_xor_sync(0xffffffffu, mx0, o));
            mx1 = fmaxf(mx1, __shfl_xor_sync(0xffffffffu, mx1, o));
        }
        float sm0 = 0.f, sm1 = 0.f;
        #pragma unroll
        for (int nt = 0; nt < 8; ++nt) {
            s[nt][0] = __expf(s[nt][0] - mx0); sm0 += s[nt][0];
            s[nt][1] = __expf(s[nt][1] - mx0); sm0 += s[nt][1];
            s[nt][2] = __expf(s[nt][2] - mx1); sm1 += s[nt][2];
            s[nt][3] = __expf(s[nt][3] - mx1); sm1 += s[nt][3];
        }
        #pragma unroll
        for (int o = 1; o <= 2; o <<= 1) {
            sm0 += __shfl_xor_sync(0xffffffffu, sm0, o);
            sm1 += __shfl_xor_sync(0xffffffffu, sm1, o);
        }
        float i0 = 1.f / sm0, i1 = 1.f / sm1;
        #pragma unroll
        for (int nt = 0; nt < 8; ++nt) {
            s[nt][0] *= i0; s[nt][1] *= i0;
            s[nt][2] *= i1; s[nt][3] *= i1;
        }
    }

    // ---- Phase 2: O = P @ V ----
    float o[4][4];
    #pragma unroll
    for (int nt = 0; nt < 4; ++nt)
        #pragma unroll
        for (int c = 0; c < 4; ++c) o[nt][c] = 0.f;

    const uint32_t v_row = lane & 15;
    const uint32_t v_c16 = (lane >> 4) * 16;
    #pragma unroll
    for (int kt = 0; kt < 4; ++kt) {
        // P a-frag for k-tile kt (cols 16kt..16kt+15)
        __half2 pa0 = __floats2half2_rn(s[2 * kt][0], s[2 * kt][1]);
        __half2 pa1 = __floats2half2_rn(s[2 * kt][2], s[2 * kt][3]);
        __half2 pa2 = __floats2half2_rn(s[2 * kt + 1][0], s[2 * kt + 1][1]);
        __half2 pa3 = __floats2half2_rn(s[2 * kt + 1][2], s[2 * kt + 1][3]);
        uint32_t a0 = *(uint32_t*)&pa0, a1 = *(uint32_t*)&pa1;
        uint32_t a2 = *(uint32_t*)&pa2, a3 = *(uint32_t*)&pa3;
        // V b-frags: rows (tokens) 16kt.., dims via trans
        uint32_t vb0[4], vb1[4];
        ldsm4t(vb0, sV + (kt * 16 + v_row) * AROWB + v_c16);
        ldsm4t(vb1, sV + (kt * 16 + v_row) * AROWB + 32 + v_c16);
        MMA_F16(o[0], a0, a1, a2, a3, vb0[0], vb0[1]);
        MMA_F16(o[1], a0, a1, a2, a3, vb0[2], vb0[3]);
        MMA_F16(o[2], a0, a1, a2, a3, vb1[0], vb1[1]);
        MMA_F16(o[3], a0, a1, a2, a3, vb1[2], vb1[3]);
    }

    // ---- write O (fp16) to (BW, N, DIM) at head offset ----
    __half* obase = outh + (size_t)bw * NTOK * DIM_ + (size_t)h * HD_;
    #pragma unroll
    for (int nt = 0; nt < 4; ++nt) {
        int c = nt * 8 + cbase;
        __half2 h0 = __floats2half2_rn(o[nt][0], o[nt][1]);
        __half2 h1 = __floats2half2_rn(o[nt][2], o[nt][3]);
        *(__half2*)(obase + (size_t)r * DIM_ + c) = h0;
        *(__half2*)(obase + (size_t)(r + 8) * DIM_ + c) = h1;
    }
}

// ---------------------------------------------------------------------------
extern "C" void kernel_launch(void* const* d_in, const int* in_sizes, int n_in,
                              void* d_out, int out_size)
{
    const float* x       = (const float*)d_in[0];
    const float* mask    = (const float*)d_in[1];
    const float* qkv_w   = (const float*)d_in[2];
    const float* qkv_b   = (const float*)d_in[3];
    const float* table   = (const float*)d_in[4];
    const float* proj_w  = (const float*)d_in[5];
    const float* proj_b  = (const float*)d_in[6];
    const int*   rel_idx = (const int*)d_in[7];
    float* out = (float*)d_out;

    __half *qkvh, *xh, *ah, *w1h, *w2h;
    float *b1, *bias;
    cudaGetSymbolAddress((void**)&qkvh, g_qkvh);
    cudaGetSymbolAddress((void**)&xh, g_xh);
    cudaGetSymbolAddress((void**)&ah, g_ah);
    cudaGetSymbolAddress((void**)&w1h, g_w1h);
    cudaGetSymbolAddress((void**)&w2h, g_w2h);
    cudaGetSymbolAddress((void**)&b1, g_b1);
    cudaGetSymbolAddress((void**)&bias, g_bias);

    const int gemm_smem = NSTAGE * STAGE_B;   // 61440
    cudaFuncSetAttribute(gemm_h<__half>, cudaFuncAttributeMaxDynamicSharedMemorySize,
                         gemm_smem);
    cudaFuncSetAttribute(gemm_h<float>, cudaFuncAttributeMaxDynamicSharedMemorySize,
                         gemm_smem);

    // 1) prep
    {
        int n1 = MTOT * DIM_;
        convert_half<<<n1 / 4 / 256, 256>>>(x, xh, n1);
        convert_w1<<<TRIPLE * DIM_ / 4 / 256, 256>>>(qkv_w, w1h);
        int n3 = DIM_ * DIM_;
        convert_half<<<n3 / 4 / 256, 256>>>(proj_w, w2h, n3);
        prep_misc<<<64, 256>>>(qkv_b, b1, table, rel_idx, bias);
    }
    // 2) QKV GEMM -> fp16 qkv
    {
        dim3 grid(TRIPLE / 128, MTOT / 128);
        gemm_h<__half><<<grid, 256, gemm_smem>>>(xh, w1h, b1, qkvh, TRIPLE, DIM_);
    }
    // 3) attention (tensor-core)
    {
        dim3 grid(NH_, BW_);
        attn_mma<<<grid, 128>>>(qkvh, mask, bias, ah);
    }
    // 4) proj GEMM -> fp32 out
    {
        dim3 grid(DIM_ / 128, MTOT / 128);
        gemm_h<float><<<grid, 256, gemm_smem>>>(ah, w2h, proj_b, out, DIM_, DIM_);
    }
}